// round 13
// baseline (speedup 1.0000x reference)
#include <cuda_runtime.h>
#include <cstdint>

// OptFP_Embedding: out[b,f,:] = beta + sum_i c_i(g) * clip(rint((W[x]-beta)*ia_i), lo_i, hi_i)
//   c_i = softmax(gamma)_i * (|alpha_i|+eps); sum_i softmax = 1 folds beta out.
//
// Strategy: R10 structure (cp.async depth-6, 7 blocks/SM) + L2 RESIDENCY CONTROL.
//   Row cp.asyncs and group gathers carry an evict_last cache policy
//   (policy-operand form: ld.global.nc.L2::cache_hint / cp.async...L2::cache_hint,
//   which is the encoding sm_100 ptxas accepts for scalar widths).
//   Outputs stay evict-first (__stcs). Steady-state DRAM -> output writes only.
//
// Inputs (metadata order):
//   d_in[0] = x           int32   [4096*39]
//   d_in[1] = weight      float32 [1000000*64]
//   d_in[2] = group_index int32   [1000000]
//   d_in[3] = gamma       float32 [8*1*3]
//   d_in[4] = alpha       float32 [3]
//   d_in[5] = beta        float32 [64]
// Output: float32 [4096*39*64]

#define EMB_DIM 64
#define GROUPS 8
#define NBITS 3
#define TPT 16                    // threads per token (16 x float4 = 64 floats)
#define BLOCK_THREADS 256
#define SUBS (BLOCK_THREADS / TPT)        // 16 tokens per stage
#define STAGES 6                          // cp.async pipeline depth
#define TOKENS_PER_BLOCK (SUBS * STAGES)  // 96

__device__ __forceinline__ uint64_t policy_evict_last() {
    uint64_t p;
    asm("createpolicy.fractional.L2::evict_last.b64 %0, 1.0;" : "=l"(p));
    return p;
}

__device__ __forceinline__ void cp_async16_el(uint32_t smem_addr,
                                              const void* gptr,
                                              uint64_t policy) {
    asm volatile("cp.async.cg.shared.global.L2::cache_hint [%0], [%1], 16, %2;"
                 :: "r"(smem_addr), "l"(gptr), "l"(policy));
}

__device__ __forceinline__ void cp_commit() {
    asm volatile("cp.async.commit_group;");
}

template <int N>
__device__ __forceinline__ void cp_wait() {
    asm volatile("cp.async.wait_group %0;" :: "n"(N));
}

// policy-operand form: legal for scalar .b32 on sm_100 (the .L2::evict_last
// direct suffix is v8.b32/v4.b64-only and was rejected by ptxas in R11)
__device__ __forceinline__ int ldg_hint_s32(const int* p, uint64_t policy) {
    int v;
    asm("ld.global.nc.L2::cache_hint.b32 %0, [%1], %2;"
        : "=r"(v) : "l"(p), "l"(policy));
    return v;
}

__global__ __launch_bounds__(BLOCK_THREADS, 7)
void optfp_embedding_kernel(const int* __restrict__ x,
                            const float* __restrict__ weight,
                            const int* __restrict__ group_index,
                            const float* __restrict__ gamma,
                            const float* __restrict__ alpha,
                            const float* __restrict__ beta,
                            float* __restrict__ out,
                            int ntok) {
    __shared__ float4 s_rows[STAGES][BLOCK_THREADS];   // 24 KB staging
    __shared__ float s_beta[EMB_DIM];
    __shared__ float s_c[GROUPS][NBITS];    // softmax(gamma)_i * (|alpha_i|+eps)
    __shared__ float s_ia[NBITS];           // 1 / (|alpha_i| + eps)

    const int tid = threadIdx.x;

    // ---- one-time coefficient tables ----
    if (tid < EMB_DIM) s_beta[tid] = beta[tid];
    if (tid < GROUPS) {
        // TAU = 1.0
        float g0 = gamma[tid * NBITS + 0];
        float g1 = gamma[tid * NBITS + 1];
        float g2 = gamma[tid * NBITS + 2];
        float m = fmaxf(g0, fmaxf(g1, g2));
        float e0 = __expf(g0 - m);
        float e1 = __expf(g1 - m);
        float e2 = __expf(g2 - m);
        float inv = 1.0f / (e0 + e1 + e2);
        s_c[tid][0] = e0 * inv * (fabsf(alpha[0]) + 1e-10f);
        s_c[tid][1] = e1 * inv * (fabsf(alpha[1]) + 1e-10f);
        s_c[tid][2] = e2 * inv * (fabsf(alpha[2]) + 1e-10f);
        if (tid == 0) {
            s_ia[0] = 1.0f / (fabsf(alpha[0]) + 1e-10f);
            s_ia[1] = 1.0f / (fabsf(alpha[1]) + 1e-10f);
            s_ia[2] = 1.0f / (fabsf(alpha[2]) + 1e-10f);
        }
    }

    const int sub  = tid >> 4;            // 0..15 : token slot within a stage
    const int lane = tid & (TPT - 1);     // 0..15 : 16B chunk within a row

    const unsigned base = (unsigned)blockIdx.x * TOKENS_PER_BLOCK + sub;
    const uint64_t pol = policy_evict_last();

    // ---- prologue: front-batched index gathers ----
    int idx[STAGES];
#pragma unroll
    for (int s = 0; s < STAGES; s++) {
        const unsigned tok = base + (unsigned)s * SUBS;
        idx[s] = (tok < (unsigned)ntok) ? __ldg(x + tok) : 0;
    }

    // group ids: 6 gathers (evict_last policy: 4MB table stays L2-resident),
    // packed into one register (4-bit fields)
    unsigned gpack = 0;
#pragma unroll
    for (int s = 0; s < STAGES; s++)
        gpack |= ((unsigned)ldg_hint_s32(group_index + idx[s], pol)) << (s * 4);

    // Table visibility barrier BEFORE staging traffic starts.
    __syncthreads();

    // ---- issue depth-6 cp.async row gathers with evict_last policy ----
    const uint32_t smem_row = (uint32_t)__cvta_generic_to_shared(&s_rows[0][tid]);
#pragma unroll
    for (int s = 0; s < STAGES; s++) {
        cp_async16_el(smem_row + (uint32_t)(s * BLOCK_THREADS * sizeof(float4)),
                      (const float4*)weight + (((unsigned)idx[s]) << 4) + lane,
                      pol);
        cp_commit();
    }

    const float4 b4 = ((const float4*)s_beta)[lane];
    const float ia0 = s_ia[0], ia1 = s_ia[1], ia2 = s_ia[2];

    // ---- drain pipeline: compute one stage as each copy lands ----
#pragma unroll
    for (int s = 0; s < STAGES; s++) {
        switch (STAGES - 1 - s) {   // cp.async.wait_group needs an immediate
            case 5: cp_wait<5>(); break;
            case 4: cp_wait<4>(); break;
            case 3: cp_wait<3>(); break;
            case 2: cp_wait<2>(); break;
            case 1: cp_wait<1>(); break;
            default: cp_wait<0>(); break;
        }
        const unsigned tok = base + (unsigned)s * SUBS;
        if (tok >= (unsigned)ntok) continue;

        const float4 w = s_rows[s][tid];
        const int g = (gpack >> (s * 4)) & 7;
        const float c0 = s_c[g][0];
        const float c1 = s_c[g][1];
        const float c2 = s_c[g][2];

        const float wv[4] = {w.x, w.y, w.z, w.w};
        const float bv[4] = {b4.x, b4.y, b4.z, b4.w};
        float rv[4];
#pragma unroll
        for (int c = 0; c < 4; c++) {
            const float wb = wv[c] - bv[c];
            const float r0 = fminf(fmaxf(rintf(wb * ia0),   -2.0f),   1.0f);
            const float r1 = fminf(fmaxf(rintf(wb * ia1),   -8.0f),   7.0f);
            const float r2 = fminf(fmaxf(rintf(wb * ia2), -128.0f), 127.0f);
            float acc = fmaf(c0, r0, bv[c]);
            acc = fmaf(c1, r1, acc);
            rv[c] = fmaf(c2, r2, acc);
        }
        float4 r; r.x = rv[0]; r.y = rv[1]; r.z = rv[2]; r.w = rv[3];
        // evict-first streaming store: keeps output from polluting the
        // evict_last row/group working set in L2.
        __stcs((float4*)out + tok * TPT + lane, r);
    }
}

extern "C" void kernel_launch(void* const* d_in, const int* in_sizes, int n_in,
                              void* d_out, int out_size) {
    const int*   x           = (const int*)d_in[0];
    const float* weight      = (const float*)d_in[1];
    const int*   group_index = (const int*)d_in[2];
    const float* gamma       = (const float*)d_in[3];
    const float* alpha       = (const float*)d_in[4];
    const float* beta        = (const float*)d_in[5];
    float* out = (float*)d_out;

    const int ntok = in_sizes[0];  // 4096 * 39 = 159744 = 96 * 1664
    const int blocks = (ntok + TOKENS_PER_BLOCK - 1) / TOKENS_PER_BLOCK;
    optfp_embedding_kernel<<<blocks, BLOCK_THREADS>>>(
        x, weight, group_index, gamma, alpha, beta, out, ntok);
}